// round 11
// baseline (speedup 1.0000x reference)
#include <cuda_runtime.h>
#include <cuda_fp16.h>
#include <cstdint>

// ---------------- SMEM layout (bytes) ----------------
#define SM_BIAS   0                     // 256 floats
#define SM_BPROJ  1024                  // 16 floats
#define SM_W      1088                  // W image: 256 rows x 560B = 143360
#define W_STRIDE  560                   // 280 halves (256 h-cols + 24 x-cols), conflict-free
#define SM_WP     (1088 + 143360)       // 144448: W_proj 12 rows x 528B = 6336
#define WP_STRIDE 528
#define SM_SCR    (144448 + 6336)       // 150784: scratch, 3 groups x 9216 (NOT aliased)
#define SCR_GRP   9216
#define SM_A      (150784 + 27648)      // 178432: A fp16 staging, 3 groups x 17920
#define A_GRP     17920                 // 32 rows x 560B
#define A_STRIDE  560
#define SM_TOTAL  (178432 + 3 * 17920)  // 232192  (<= 232448 limit)

#define W_U4   8960                     // 143360 / 16
#define WP_U4  396                      // 6336 / 16

// Pre-converted fp16 weight images (static device scratch — no allocation)
__device__ uint4 g_w[W_U4];             // [n 0..255][k 0..279]; k<256=W_hh, 256..279=W_ih
__device__ uint4 g_wp[WP_U4];           // [n 0..11][k 0..263]; k<256=W_proj else 0

static __device__ __forceinline__ uint32_t smem_u32(const void* p) {
    uint32_t r;
    asm("{ .reg .u64 t; cvta.to.shared.u64 t, %1; cvt.u32.u64 %0, t; }" : "=r"(r) : "l"(p));
    return r;
}
static __device__ __forceinline__ uint32_t pack2(float a, float b) {
    __half2 h = __floats2half2_rn(a, b);
    return *reinterpret_cast<uint32_t*>(&h);
}
static __device__ __forceinline__ void cp16(uint32_t dst, const void* src) {
    asm volatile("cp.async.cg.shared.global [%0], [%1], 16;" :: "r"(dst), "l"(src));
}
#define CP_COMMIT()  asm volatile("cp.async.commit_group;" ::: "memory")
#define CP_WAIT(n)   asm volatile("cp.async.wait_group %0;" :: "n"(n) : "memory")

static __device__ __forceinline__ void lds32(uint32_t& v, uint32_t a) {
    asm volatile("ld.shared.b32 %0, [%1];" : "=r"(v) : "r"(a));
}
static __device__ __forceinline__ void ldsf2(float& v0, float& v1, uint32_t a) {
    asm volatile("ld.shared.v2.f32 {%0,%1}, [%2];" : "=f"(v0), "=f"(v1) : "r"(a));
}
static __device__ __forceinline__ void stsf2(uint32_t a, float v0, float v1) {
    asm volatile("st.shared.v2.f32 [%0], {%1,%2};" :: "r"(a), "f"(v0), "f"(v1));
}
static __device__ __forceinline__ void sts32(uint32_t a, uint32_t v) {
    asm volatile("st.shared.b32 [%0], %1;" :: "r"(a), "r"(v));
}
static __device__ __forceinline__ void sts64(uint32_t a, uint32_t v0, uint32_t v1) {
    asm volatile("st.shared.v2.b32 [%0], {%1,%2};" :: "r"(a), "r"(v0), "r"(v1));
}
static __device__ __forceinline__ void ldmatrix4(uint32_t& a0, uint32_t& a1,
                                                 uint32_t& a2, uint32_t& a3, uint32_t addr) {
    asm volatile("ldmatrix.sync.aligned.m8n8.x4.shared.b16 {%0,%1,%2,%3}, [%4];"
                 : "=r"(a0), "=r"(a1), "=r"(a2), "=r"(a3) : "r"(addr));
}
static __device__ __forceinline__ void ldmatrix2(uint32_t& a0, uint32_t& a1, uint32_t addr) {
    asm volatile("ldmatrix.sync.aligned.m8n8.x2.shared.b16 {%0,%1}, [%2];"
                 : "=r"(a0), "=r"(a1) : "r"(addr));
}
#define MMA16816(c0, c1, c2, c3, a0, a1, a2, a3, b0, b1)                          \
    asm volatile("mma.sync.aligned.m16n8k16.row.col.f32.f16.f16.f32 "             \
                 "{%0,%1,%2,%3},{%4,%5,%6,%7},{%8,%9},{%0,%1,%2,%3};"             \
                 : "+f"(c0), "+f"(c1), "+f"(c2), "+f"(c3)                          \
                 : "r"(a0), "r"(a1), "r"(a2), "r"(a3), "r"(b0), "r"(b1))
#define MMA16808(c0, c1, c2, c3, a0, a1, b0)                                      \
    asm volatile("mma.sync.aligned.m16n8k8.row.col.f32.f16.f16.f32 "              \
                 "{%0,%1,%2,%3},{%4,%5},{%6},{%0,%1,%2,%3};"                       \
                 : "+f"(c0), "+f"(c1), "+f"(c2), "+f"(c3)                          \
                 : "r"(a0), "r"(a1), "r"(b0))
#define BAR_GRP(id) asm volatile("bar.sync %0, 128;" :: "r"(id) : "memory")

static __device__ __forceinline__ float tanh_fast(float z) {
    float r;
    asm("tanh.approx.f32 %0, %1;" : "=f"(r) : "f"(z));
    return r;
}

// ================= prep: fp32 -> fp16 padded weight images =================
__global__ void prep_kernel(const float* __restrict__ W_ih, const float* __restrict__ W_hh,
                            const float* __restrict__ W_proj) {
    int idx = blockIdx.x * 256 + threadIdx.x;
    if (idx < 256 * 280) {
        int n = idx / 280, k = idx % 280;
        float v = (k < 256) ? W_hh[n * 256 + k] : W_ih[n * 24 + (k - 256)];
        reinterpret_cast<__half*>(g_w)[idx] = __float2half_rn(v);
    } else if (idx < 256 * 280 + 12 * 264) {
        int r = idx - 256 * 280;          // 0 .. 3167
        int n = r / 264, k = r % 264;
        float v = (k < 256) ? W_proj[n * 256 + k] : 0.0f;
        reinterpret_cast<__half*>(g_wp)[r] = __float2half_rn(v);
    }
}

// ====== persistent fused kernel: 384 thr; 3 groups x 4 warps; pipelined fragments ======
__global__ void __launch_bounds__(384, 1)
rnn_kernel(const float* __restrict__ xin, const float* __restrict__ hidden,
           const float* __restrict__ b_ih, const float* __restrict__ b_hh,
           const float* __restrict__ b_proj,
           float* __restrict__ out, float* __restrict__ h_out, int ntiles) {
    extern __shared__ char smem[];
    const uint32_t sb = smem_u32(smem);
    float* sbias  = reinterpret_cast<float*>(smem + SM_BIAS);
    float* sbproj = reinterpret_cast<float*>(smem + SM_BPROJ);

    const int tid  = threadIdx.x;
    const int w    = tid >> 5;
    const int lane = tid & 31;
    const int g    = lane >> 2;          // fragment row group 0..7
    const int c0   = (lane & 3) * 2;     // fragment col base 0,2,4,6
    const int grp  = w >> 2;             // 0..2
    const int nq   = w & 3;              // N-quarter: cols [nq*64, nq*64+64)
    const int pt   = (nq << 5) | lane;   // 0..127 within group

    // ---- resident W load (once per CTA) ----
#pragma unroll
    for (int it = 0; it < 24; it++) {
        int i = tid + it * 384;
        if (i < W_U4) cp16(sb + SM_W + i * 16, g_w + i);
    }
#pragma unroll
    for (int it = 0; it < 2; it++) {
        int i = tid + it * 384;
        if (i < WP_U4) cp16(sb + SM_WP + i * 16, g_wp + i);
    }
    CP_COMMIT();
    if (tid < 256) sbias[tid] = b_ih[tid] + b_hh[tid];
    if (tid < 16) sbproj[tid] = (tid < 12) ? b_proj[tid] : 0.0f;
    CP_WAIT(0);
    __syncthreads();

    // ---- ldmatrix B base (matrix m = lane>>3: nt-parity m>>1, k-half m&1) ----
    const int mrole = lane >> 3, mrow = lane & 7;
    const uint32_t wq0 = sb + SM_W +
        (uint32_t)((nq * 64 + (mrole >> 1) * 8 + mrow) * W_STRIDE) + (mrole & 1) * 16;
    // k8-tail B base: lanes 0..15 = 16 consecutive n-rows (2 n-tiles), k bytes 544..559
    const uint32_t wt0 = sb + SM_W + (uint32_t)((nq * 64 + (lane & 15)) * W_STRIDE) + 544;
    // proj B bases: this quarter's K-chunk, n-tiles 0 and 1 (rows 12..15 read garbage, discarded)
    const uint32_t pbase = sb + SM_WP + (uint32_t)(nq * 128) + (lane & 3) * 4;
    const uint32_t pb0 = pbase + (uint32_t)(g * WP_STRIDE);
    const uint32_t pb1 = pbase + (uint32_t)((8 + g) * WP_STRIDE);
    // this group's A staging buffer + dedicated (non-aliased) scratch
    const uint32_t ab   = sb + SM_A + (uint32_t)grp * A_GRP;
    const uint32_t am0  = ab + (uint32_t)(lane & 15) * A_STRIDE + (lane >> 4) * 16;
    const uint32_t am1  = am0 + 16 * A_STRIDE;
    const uint32_t scrG = sb + SM_SCR + (uint32_t)grp * SCR_GRP;
    const uint32_t scrW = scrG + (uint32_t)nq * 2304;
    const int barid = grp + 1;

    const int ngrp = gridDim.x * 3;
    int t = blockIdx.x * 3 + grp;

    // ---- prologue: stage first tile ----
    {
        const float4* hsrc = (const float4*)(hidden + (size_t)t * 32 * 256);
#pragma unroll
        for (int j = 0; j < 16; j++) {
            const int f4 = j * 128 + pt;
            float4 v = hsrc[f4];
            sts64(ab + (uint32_t)(f4 >> 6) * A_STRIDE + (f4 & 63) * 8,
                  pack2(v.x, v.y), pack2(v.z, v.w));
        }
        const float2* xsrc = (const float2*)(xin + (size_t)t * 32 * 24);
#pragma unroll
        for (int j = 0; j < 3; j++) {
            const int j2 = j * 128 + pt;
            const int row = j2 / 12, cc = j2 % 12;
            float2 f = xsrc[j2];
            sts32(ab + (uint32_t)row * A_STRIDE + 512 + cc * 4, pack2(f.x, f.y));
        }
    }

    for (; t < ntiles; t += ngrp) {
        const size_t r0 = (size_t)t * 32;

        // ---- acc init = bias ----
        float acc[64];
#pragma unroll
        for (int q = 0; q < 4; q++)
#pragma unroll
            for (int nt = 0; nt < 2; nt++) {
                float2 bb = *(const float2*)(sbias + nq * 64 + q * 16 + nt * 8 + c0);
                const int i = q * 16 + nt * 8;
                acc[i + 0] = bb.x; acc[i + 1] = bb.y; acc[i + 2] = bb.x; acc[i + 3] = bb.y;
                acc[i + 4] = bb.x; acc[i + 5] = bb.y; acc[i + 6] = bb.x; acc[i + 7] = bb.y;
            }

        BAR_GRP(barid);   // B0: staged A visible to whole group

        // ---- MMA1: 17 full k16 steps, software-pipelined fragments ----
        uint32_t Ac[8], An[8], Bc[4], Bn[4];
        ldmatrix4(Ac[0], Ac[1], Ac[2], Ac[3], am0);
        ldmatrix4(Ac[4], Ac[5], Ac[6], Ac[7], am1);
        ldmatrix4(Bc[0], Bc[1], Bc[2], Bc[3], wq0);
#pragma unroll
        for (int ks = 0; ks < 17; ks++) {
            if (ks < 16) {
                ldmatrix4(An[0], An[1], An[2], An[3], am0 + (ks + 1) * 32);
                ldmatrix4(An[4], An[5], An[6], An[7], am1 + (ks + 1) * 32);
            }
#pragma unroll
            for (int q = 0; q < 4; q++) {
                if (q < 3)
                    ldmatrix4(Bn[0], Bn[1], Bn[2], Bn[3],
                              wq0 + (uint32_t)(q + 1) * (16 * W_STRIDE) + ks * 32);
                else if (ks < 16)
                    ldmatrix4(Bn[0], Bn[1], Bn[2], Bn[3], wq0 + (ks + 1) * 32);
                const int i = q * 16;
                MMA16816(acc[i + 0], acc[i + 1], acc[i + 2], acc[i + 3],
                         Ac[0], Ac[1], Ac[2], Ac[3], Bc[0], Bc[1]);
                MMA16816(acc[i + 4], acc[i + 5], acc[i + 6], acc[i + 7],
                         Ac[4], Ac[5], Ac[6], Ac[7], Bc[0], Bc[1]);
                MMA16816(acc[i + 8], acc[i + 9], acc[i + 10], acc[i + 11],
                         Ac[0], Ac[1], Ac[2], Ac[3], Bc[2], Bc[3]);
                MMA16816(acc[i + 12], acc[i + 13], acc[i + 14], acc[i + 15],
                         Ac[4], Ac[5], Ac[6], Ac[7], Bc[2], Bc[3]);
#pragma unroll
                for (int z = 0; z < 4; z++) Bc[z] = Bn[z];
            }
#pragma unroll
            for (int z = 0; z < 8; z++) Ac[z] = An[z];
        }
        // ---- k8 tail: k 272..279 (x cols 16..23) ----
        {
            uint32_t a0, a1, a4, a5;
            ldmatrix2(a0, a1, am0 + 544);
            ldmatrix2(a4, a5, am1 + 544);
#pragma unroll
            for (int q = 0; q < 4; q++) {
                uint32_t b0, b1;
                ldmatrix2(b0, b1, wt0 + (uint32_t)q * (16 * W_STRIDE));
                const int i = q * 16;
                MMA16808(acc[i + 0], acc[i + 1], acc[i + 2], acc[i + 3],  a0, a1, b0);
                MMA16808(acc[i + 4], acc[i + 5], acc[i + 6], acc[i + 7],  a4, a5, b0);
                MMA16808(acc[i + 8], acc[i + 9], acc[i + 10], acc[i + 11], a0, a1, b1);
                MMA16808(acc[i + 12], acc[i + 13], acc[i + 14], acc[i + 15], a4, a5, b1);
            }
        }

        // ---- tanh + store h_new (this warp's 32 rows x 64 cols) ----
#pragma unroll
        for (int i = 0; i < 64; i++) acc[i] = tanh_fast(acc[i]);

        float* hp = h_out + (r0 + g) * 256 + nq * 64;
#pragma unroll
        for (int q = 0; q < 4; q++)
#pragma unroll
            for (int nt = 0; nt < 2; nt++) {
                const int i = q * 16 + nt * 8;
                const int n = q * 16 + nt * 8 + c0;
                *(float2*)(hp + n)             = make_float2(acc[i + 0], acc[i + 1]);
                *(float2*)(hp + 8 * 256 + n)   = make_float2(acc[i + 2], acc[i + 3]);
                *(float2*)(hp + 16 * 256 + n)  = make_float2(acc[i + 4], acc[i + 5]);
                *(float2*)(hp + 24 * 256 + n)  = make_float2(acc[i + 6], acc[i + 7]);
            }

        // ---- proj partials: 32 rows x 16 cols over this quarter's K=64 ----
        float pa[16];
#pragma unroll
        for (int i = 0; i < 16; i++) pa[i] = 0.0f;
#pragma unroll
        for (int pk = 0; pk < 4; pk++) {
            const int i = pk * 16;
            const uint32_t a0 = pack2(acc[i + 0],  acc[i + 1]);
            const uint32_t a1 = pack2(acc[i + 2],  acc[i + 3]);
            const uint32_t a2 = pack2(acc[i + 8],  acc[i + 9]);
            const uint32_t a3 = pack2(acc[i + 10], acc[i + 11]);
            const uint32_t a4 = pack2(acc[i + 4],  acc[i + 5]);
            const uint32_t a5 = pack2(acc[i + 6],  acc[i + 7]);
            const uint32_t a6 = pack2(acc[i + 12], acc[i + 13]);
            const uint32_t a7 = pack2(acc[i + 14], acc[i + 15]);
            uint32_t b00, b01, b10, b11;
            lds32(b00, pb0 + pk * 32); lds32(b01, pb0 + pk * 32 + 16);
            lds32(b10, pb1 + pk * 32); lds32(b11, pb1 + pk * 32 + 16);
            MMA16816(pa[0],  pa[1],  pa[2],  pa[3],  a0, a1, a2, a3, b00, b01);
            MMA16816(pa[4],  pa[5],  pa[6],  pa[7],  a4, a5, a6, a7, b00, b01);
            MMA16816(pa[8],  pa[9],  pa[10], pa[11], a0, a1, a2, a3, b10, b11);
            MMA16816(pa[12], pa[13], pa[14], pa[15], a4, a5, a6, a7, b10, b11);
        }

        // ---- prefetch next tile's A/x, packed to fp16 in two batches (low reg peak) ----
        const int tn = t + ngrp;
        const bool pf = tn < ntiles;
        uint32_t pv2[32];
        float2 px[3];
        if (pf) {
            const float4* hsrc = (const float4*)(hidden + (size_t)tn * 32 * 256);
            {
                float4 tmp[8];
#pragma unroll
                for (int j = 0; j < 8; j++) tmp[j] = hsrc[j * 128 + pt];
#pragma unroll
                for (int j = 0; j < 8; j++) {
                    pv2[2 * j]     = pack2(tmp[j].x, tmp[j].y);
                    pv2[2 * j + 1] = pack2(tmp[j].z, tmp[j].w);
                }
            }
            {
                float4 tmp[8];
#pragma unroll
                for (int j = 0; j < 8; j++) tmp[j] = hsrc[(j + 8) * 128 + pt];
#pragma unroll
                for (int j = 0; j < 8; j++) {
                    pv2[16 + 2 * j] = pack2(tmp[j].x, tmp[j].y);
                    pv2[17 + 2 * j] = pack2(tmp[j].z, tmp[j].w);
                }
            }
            const float2* xsrc = (const float2*)(xin + (size_t)tn * 32 * 24);
#pragma unroll
            for (int j = 0; j < 3; j++) px[j] = xsrc[j * 128 + pt];
        }

        // ---- write 32x16 partials to this warp's scratch region ----
#pragma unroll
        for (int nt = 0; nt < 2; nt++)
#pragma unroll
            for (int half = 0; half < 2; half++) {
                const int i = nt * 8 + half * 4;
                const uint32_t base = scrW + (uint32_t)((g + half * 16) * 72 + (nt * 8 + c0) * 4);
                stsf2(base,          pa[i + 0], pa[i + 1]);
                stsf2(base + 8 * 72, pa[i + 2], pa[i + 3]);
            }
        BAR_GRP(barid);   // B2: partials visible (and all warps past mainloop)

        // ---- sum 4 partials; warp nq handles tile rows nq*8+g; quad = 1 row ----
        float l[4];
        l[0] = sbproj[c0]; l[1] = sbproj[c0 + 1];
        l[2] = sbproj[8 + c0]; l[3] = sbproj[9 + c0];
        {
            const uint32_t rbase = scrG + (uint32_t)((nq * 8 + g) * 72);
#pragma unroll
            for (int j = 0; j < 4; j++) {
                float p0, p1;
                ldsf2(p0, p1, rbase + j * 2304 + c0 * 4);
                l[0] += p0; l[1] += p1;
                ldsf2(p0, p1, rbase + j * 2304 + (8 + c0) * 4);
                l[2] += p0; l[3] += p1;
            }
        }

        {
            const bool v1 = (8 + c0) < 12;
            if (!v1) { l[2] = l[3] = -1e30f; }

            float mx = fmaxf(fmaxf(l[0], l[1]), fmaxf(l[2], l[3]));
            mx = fmaxf(mx, __shfl_xor_sync(0xFFFFFFFFu, mx, 1));
            mx = fmaxf(mx, __shfl_xor_sync(0xFFFFFFFFu, mx, 2));

            float s = 0.f;
#pragma unroll
            for (int j = 0; j < 4; j++) { l[j] = __expf(l[j] - mx); s += l[j]; }
            s += __shfl_xor_sync(0xFFFFFFFFu, s, 1);
            s += __shfl_xor_sync(0xFFFFFFFFu, s, 2);
            const float inv = __fdividef(1.0f, s);

            float* o = out + (r0 + nq * 8 + g) * 12;
            *(float2*)(o + c0) = make_float2(l[0] * inv, l[1] * inv);
            if (v1) *(float2*)(o + 8 + c0) = make_float2(l[2] * inv, l[3] * inv);
        }

        // ---- store prefetched next-tile A/x (after B2: all group A-reads done) ----
        if (pf) {
#pragma unroll
            for (int j = 0; j < 16; j++) {
                const int f4 = j * 128 + pt;
                sts64(ab + (uint32_t)(f4 >> 6) * A_STRIDE + (f4 & 63) * 8,
                      pv2[2 * j], pv2[2 * j + 1]);
            }
#pragma unroll
            for (int j = 0; j < 3; j++) {
                const int j2 = j * 128 + pt;
                const int row = j2 / 12, cc = j2 % 12;
                sts32(ab + (uint32_t)row * A_STRIDE + 512 + cc * 4, pack2(px[j].x, px[j].y));
            }
        }
    }
}

extern "C" void kernel_launch(void* const* d_in, const int* in_sizes, int n_in,
                              void* d_out, int out_size) {
    const float* x      = (const float*)d_in[0];
    const float* hidden = (const float*)d_in[1];
    const float* W_ih   = (const float*)d_in[2];
    const float* b_ih   = (const float*)d_in[3];
    const float* W_hh   = (const float*)d_in[4];
    const float* b_hh   = (const float*)d_in[5];
    const float* W_proj = (const float*)d_in[6];
    const float* b_proj = (const float*)d_in[7];

    const int N = in_sizes[0] / 24;            // 524288
    float* out   = (float*)d_out;              // [N,12] softmax
    float* h_out = out + (size_t)N * 12;       // [N,256] h_new

    cudaFuncSetAttribute(rnn_kernel, cudaFuncAttributeMaxDynamicSharedMemorySize, SM_TOTAL);

    prep_kernel<<<293, 256>>>(W_ih, W_hh, W_proj);               // 74848 elems (guarded)
    rnn_kernel<<<152, 384, SM_TOTAL>>>(x, hidden, b_ih, b_hh, b_proj,
                                       out, h_out, N / 32);      // persistent; tiles of 32 rows
}

// round 12
// speedup vs baseline: 1.0770x; 1.0770x over previous
#include <cuda_runtime.h>
#include <cuda_fp16.h>
#include <cstdint>

// ---------------- SMEM layout (bytes) ----------------
#define SM_BIAS   0                     // 256 floats
#define SM_BPROJ  1024                  // 16 floats
#define SM_W      1088                  // W image: 256 rows x 560B = 143360
#define W_STRIDE  560                   // 280 halves (256 h-cols + 24 x-cols), conflict-free
#define SM_WP     (1088 + 143360)       // 144448: W_proj 12 rows x 528B = 6336
#define WP_STRIDE 528
#define SM_A      (144448 + 6336)       // 150784: A fp16 staging, 4 groups x 17920
#define A_GRP     17920                 // 32 rows x 560B
#define A_STRIDE  560
#define SM_TOTAL  (150784 + 4 * 17920)  // 222464  (<= 232448 limit)

#define W_U4   8960                     // 143360 / 16
#define WP_U4  396                      // 6336 / 16

// Pre-converted fp16 weight images (static device scratch — no allocation)
__device__ uint4 g_w[W_U4];             // [n 0..255][k 0..279]; k<256=W_hh, 256..279=W_ih
__device__ uint4 g_wp[WP_U4];           // [n 0..11][k 0..263]; k<256=W_proj else 0

static __device__ __forceinline__ uint32_t smem_u32(const void* p) {
    uint32_t r;
    asm("{ .reg .u64 t; cvta.to.shared.u64 t, %1; cvt.u32.u64 %0, t; }" : "=r"(r) : "l"(p));
    return r;
}
static __device__ __forceinline__ uint32_t pack2(float a, float b) {
    __half2 h = __floats2half2_rn(a, b);
    return *reinterpret_cast<uint32_t*>(&h);
}
static __device__ __forceinline__ void cp16(uint32_t dst, const void* src) {
    asm volatile("cp.async.cg.shared.global [%0], [%1], 16;" :: "r"(dst), "l"(src));
}
#define CP_COMMIT()  asm volatile("cp.async.commit_group;" ::: "memory")
#define CP_WAIT(n)   asm volatile("cp.async.wait_group %0;" :: "n"(n) : "memory")

static __device__ __forceinline__ void lds32(uint32_t& v, uint32_t a) {
    asm volatile("ld.shared.b32 %0, [%1];" : "=r"(v) : "r"(a));
}
static __device__ __forceinline__ void ldsf2(float& v0, float& v1, uint32_t a) {
    asm volatile("ld.shared.v2.f32 {%0,%1}, [%2];" : "=f"(v0), "=f"(v1) : "r"(a));
}
static __device__ __forceinline__ void stsf2(uint32_t a, float v0, float v1) {
    asm volatile("st.shared.v2.f32 [%0], {%1,%2};" :: "r"(a), "f"(v0), "f"(v1));
}
static __device__ __forceinline__ void sts32(uint32_t a, uint32_t v) {
    asm volatile("st.shared.b32 [%0], %1;" :: "r"(a), "r"(v));
}
static __device__ __forceinline__ void sts64(uint32_t a, uint32_t v0, uint32_t v1) {
    asm volatile("st.shared.v2.b32 [%0], {%1,%2};" :: "r"(a), "r"(v0), "r"(v1));
}
static __device__ __forceinline__ void ldmatrix4(uint32_t& a0, uint32_t& a1,
                                                 uint32_t& a2, uint32_t& a3, uint32_t addr) {
    asm volatile("ldmatrix.sync.aligned.m8n8.x4.shared.b16 {%0,%1,%2,%3}, [%4];"
                 : "=r"(a0), "=r"(a1), "=r"(a2), "=r"(a3) : "r"(addr));
}
static __device__ __forceinline__ void ldmatrix2(uint32_t& a0, uint32_t& a1, uint32_t addr) {
    asm volatile("ldmatrix.sync.aligned.m8n8.x2.shared.b16 {%0,%1}, [%2];"
                 : "=r"(a0), "=r"(a1) : "r"(addr));
}
#define MMA16816(c0, c1, c2, c3, a0, a1, a2, a3, b0, b1)                          \
    asm volatile("mma.sync.aligned.m16n8k16.row.col.f32.f16.f16.f32 "             \
                 "{%0,%1,%2,%3},{%4,%5,%6,%7},{%8,%9},{%0,%1,%2,%3};"             \
                 : "+f"(c0), "+f"(c1), "+f"(c2), "+f"(c3)                          \
                 : "r"(a0), "r"(a1), "r"(a2), "r"(a3), "r"(b0), "r"(b1))
#define MMA16808(c0, c1, c2, c3, a0, a1, b0)                                      \
    asm volatile("mma.sync.aligned.m16n8k8.row.col.f32.f16.f16.f32 "              \
                 "{%0,%1,%2,%3},{%4,%5},{%6},{%0,%1,%2,%3};"                       \
                 : "+f"(c0), "+f"(c1), "+f"(c2), "+f"(c3)                          \
                 : "r"(a0), "r"(a1), "r"(b0))
#define BAR_GRP(id) asm volatile("bar.sync %0, 128;" :: "r"(id) : "memory")

static __device__ __forceinline__ float tanh_fast(float z) {
    float r;
    asm("tanh.approx.f32 %0, %1;" : "=f"(r) : "f"(z));
    return r;
}

// ================= prep: fp32 -> fp16 padded weight images =================
__global__ void prep_kernel(const float* __restrict__ W_ih, const float* __restrict__ W_hh,
                            const float* __restrict__ W_proj) {
    int idx = blockIdx.x * 256 + threadIdx.x;
    if (idx < 256 * 280) {
        int n = idx / 280, k = idx % 280;
        float v = (k < 256) ? W_hh[n * 256 + k] : W_ih[n * 24 + (k - 256)];
        reinterpret_cast<__half*>(g_w)[idx] = __float2half_rn(v);
    } else if (idx < 256 * 280 + 12 * 264) {
        int r = idx - 256 * 280;          // 0 .. 3167
        int n = r / 264, k = r % 264;
        float v = (k < 256) ? W_proj[n * 256 + k] : 0.0f;
        reinterpret_cast<__half*>(g_wp)[r] = __float2half_rn(v);
    }
}

// ====== persistent fused kernel: 512 thr; 4 groups x 4 warps; 4 warps/SMSP ======
__global__ void __launch_bounds__(512, 1)
rnn_kernel(const float* __restrict__ xin, const float* __restrict__ hidden,
           const float* __restrict__ b_ih, const float* __restrict__ b_hh,
           const float* __restrict__ b_proj,
           float* __restrict__ out, float* __restrict__ h_out, int ntiles) {
    extern __shared__ char smem[];
    const uint32_t sb = smem_u32(smem);
    float* sbias  = reinterpret_cast<float*>(smem + SM_BIAS);
    float* sbproj = reinterpret_cast<float*>(smem + SM_BPROJ);

    const int tid  = threadIdx.x;
    const int w    = tid >> 5;
    const int lane = tid & 31;
    const int g    = lane >> 2;          // fragment row group 0..7
    const int c0   = (lane & 3) * 2;     // fragment col base 0,2,4,6
    const int grp  = w >> 2;             // 0..3
    const int nq   = w & 3;              // N-quarter: cols [nq*64, nq*64+64)
    const int pt   = (nq << 5) | lane;   // 0..127 within group

    // ---- resident W load (once per CTA) ----
#pragma unroll
    for (int it = 0; it < 18; it++) {
        int i = tid + it * 512;
        if (i < W_U4) cp16(sb + SM_W + i * 16, g_w + i);
    }
    {
        int i = tid;
        if (i < WP_U4) cp16(sb + SM_WP + i * 16, g_wp + i);
    }
    CP_COMMIT();
    if (tid < 256) sbias[tid] = b_ih[tid] + b_hh[tid];
    if (tid < 16) sbproj[tid] = (tid < 12) ? b_proj[tid] : 0.0f;
    CP_WAIT(0);
    __syncthreads();

    // ---- ldmatrix B base (matrix m = lane>>3: nt-parity m>>1, k-half m&1) ----
    const int mrole = lane >> 3, mrow = lane & 7;
    const uint32_t wq0 = sb + SM_W +
        (uint32_t)((nq * 64 + (mrole >> 1) * 8 + mrow) * W_STRIDE) + (mrole & 1) * 16;
    // k8-tail B base: lanes 0..15 = 16 consecutive n-rows (2 n-tiles), k bytes 544..559
    const uint32_t wt0 = sb + SM_W + (uint32_t)((nq * 64 + (lane & 15)) * W_STRIDE) + 544;
    // proj B bases: this quarter's K-chunk, n-tiles 0 and 1 (rows 12..15 read garbage, discarded)
    const uint32_t pbase = sb + SM_WP + (uint32_t)(nq * 128) + (lane & 3) * 4;
    const uint32_t pb0 = pbase + (uint32_t)(g * WP_STRIDE);
    const uint32_t pb1 = pbase + (uint32_t)((8 + g) * WP_STRIDE);
    // this group's A staging buffer; proj-exchange scratch ALIASES its first 9216B
    const uint32_t ab   = sb + SM_A + (uint32_t)grp * A_GRP;
    const uint32_t am0  = ab + (uint32_t)(lane & 15) * A_STRIDE + (lane >> 4) * 16;
    const uint32_t am1  = am0 + 16 * A_STRIDE;
    const uint32_t scrW = ab + (uint32_t)nq * 2304;
    const int barid = grp + 1;

    const int ngrp = gridDim.x * 4;
    int t = blockIdx.x * 4 + grp;

    // ---- prologue: stage first tile ----
    {
        const float4* hsrc = (const float4*)(hidden + (size_t)t * 32 * 256);
#pragma unroll
        for (int j = 0; j < 16; j++) {
            const int f4 = j * 128 + pt;
            float4 v = hsrc[f4];
            sts64(ab + (uint32_t)(f4 >> 6) * A_STRIDE + (f4 & 63) * 8,
                  pack2(v.x, v.y), pack2(v.z, v.w));
        }
        const float2* xsrc = (const float2*)(xin + (size_t)t * 32 * 24);
#pragma unroll
        for (int j = 0; j < 3; j++) {
            const int j2 = j * 128 + pt;
            const int row = j2 / 12, cc = j2 % 12;
            float2 f = xsrc[j2];
            sts32(ab + (uint32_t)row * A_STRIDE + 512 + cc * 4, pack2(f.x, f.y));
        }
    }

    for (; t < ntiles; t += ngrp) {
        const size_t r0 = (size_t)t * 32;

        // ---- acc init = bias ----
        float acc[64];
#pragma unroll
        for (int q = 0; q < 4; q++)
#pragma unroll
            for (int nt = 0; nt < 2; nt++) {
                float2 bb = *(const float2*)(sbias + nq * 64 + q * 16 + nt * 8 + c0);
                const int i = q * 16 + nt * 8;
                acc[i + 0] = bb.x; acc[i + 1] = bb.y; acc[i + 2] = bb.x; acc[i + 3] = bb.y;
                acc[i + 4] = bb.x; acc[i + 5] = bb.y; acc[i + 6] = bb.x; acc[i + 7] = bb.y;
            }

        BAR_GRP(barid);   // B0: staged A visible to whole group

        // ---- MMA1: 17 full k16 steps (plain loop — ptxas schedules best) ----
#pragma unroll
        for (int ks = 0; ks < 17; ks++) {
            uint32_t a0, a1, a2, a3, a4, a5, a6, a7;
            ldmatrix4(a0, a1, a2, a3, am0 + ks * 32);
            ldmatrix4(a4, a5, a6, a7, am1 + ks * 32);
#pragma unroll
            for (int q = 0; q < 4; q++) {
                uint32_t b0, b1, b2, b3;
                ldmatrix4(b0, b1, b2, b3,
                          wq0 + (uint32_t)q * (16 * W_STRIDE) + ks * 32);
                const int i = q * 16;
                MMA16816(acc[i + 0], acc[i + 1], acc[i + 2], acc[i + 3],
                         a0, a1, a2, a3, b0, b1);
                MMA16816(acc[i + 4], acc[i + 5], acc[i + 6], acc[i + 7],
                         a4, a5, a6, a7, b0, b1);
                MMA16816(acc[i + 8], acc[i + 9], acc[i + 10], acc[i + 11],
                         a0, a1, a2, a3, b2, b3);
                MMA16816(acc[i + 12], acc[i + 13], acc[i + 14], acc[i + 15],
                         a4, a5, a6, a7, b2, b3);
            }
        }
        // ---- k8 tail: k 272..279 (x cols 16..23) ----
        {
            uint32_t a0, a1, a4, a5;
            ldmatrix2(a0, a1, am0 + 544);
            ldmatrix2(a4, a5, am1 + 544);
#pragma unroll
            for (int q = 0; q < 4; q++) {
                uint32_t b0, b1;
                ldmatrix2(b0, b1, wt0 + (uint32_t)q * (16 * W_STRIDE));
                const int i = q * 16;
                MMA16808(acc[i + 0], acc[i + 1], acc[i + 2], acc[i + 3],  a0, a1, b0);
                MMA16808(acc[i + 4], acc[i + 5], acc[i + 6], acc[i + 7],  a4, a5, b0);
                MMA16808(acc[i + 8], acc[i + 9], acc[i + 10], acc[i + 11], a0, a1, b1);
                MMA16808(acc[i + 12], acc[i + 13], acc[i + 14], acc[i + 15], a4, a5, b1);
            }
        }

        // ---- tanh + store h_new (this warp's 32 rows x 64 cols) ----
#pragma unroll
        for (int i = 0; i < 64; i++) acc[i] = tanh_fast(acc[i]);

        float* hp = h_out + (r0 + g) * 256 + nq * 64;
#pragma unroll
        for (int q = 0; q < 4; q++)
#pragma unroll
            for (int nt = 0; nt < 2; nt++) {
                const int i = q * 16 + nt * 8;
                const int n = q * 16 + nt * 8 + c0;
                *(float2*)(hp + n)             = make_float2(acc[i + 0], acc[i + 1]);
                *(float2*)(hp + 8 * 256 + n)   = make_float2(acc[i + 2], acc[i + 3]);
                *(float2*)(hp + 16 * 256 + n)  = make_float2(acc[i + 4], acc[i + 5]);
                *(float2*)(hp + 24 * 256 + n)  = make_float2(acc[i + 6], acc[i + 7]);
            }

        // ---- proj partials: 32 rows x 16 cols over this quarter's K=64 ----
        float pa[16];
#pragma unroll
        for (int i = 0; i < 16; i++) pa[i] = 0.0f;
#pragma unroll
        for (int pk = 0; pk < 4; pk++) {
            const int i = pk * 16;
            const uint32_t a0 = pack2(acc[i + 0],  acc[i + 1]);
            const uint32_t a1 = pack2(acc[i + 2],  acc[i + 3]);
            const uint32_t a2 = pack2(acc[i + 8],  acc[i + 9]);
            const uint32_t a3 = pack2(acc[i + 10], acc[i + 11]);
            const uint32_t a4 = pack2(acc[i + 4],  acc[i + 5]);
            const uint32_t a5 = pack2(acc[i + 6],  acc[i + 7]);
            const uint32_t a6 = pack2(acc[i + 12], acc[i + 13]);
            const uint32_t a7 = pack2(acc[i + 14], acc[i + 15]);
            uint32_t b00, b01, b10, b11;
            lds32(b00, pb0 + pk * 32); lds32(b01, pb0 + pk * 32 + 16);
            lds32(b10, pb1 + pk * 32); lds32(b11, pb1 + pk * 32 + 16);
            MMA16816(pa[0],  pa[1],  pa[2],  pa[3],  a0, a1, a2, a3, b00, b01);
            MMA16816(pa[4],  pa[5],  pa[6],  pa[7],  a4, a5, a6, a7, b00, b01);
            MMA16816(pa[8],  pa[9],  pa[10], pa[11], a0, a1, a2, a3, b10, b11);
            MMA16816(pa[12], pa[13], pa[14], pa[15], a4, a5, a6, a7, b10, b11);
        }

        // ---- prefetch next tile's A/x, packed to fp16 in two batches (low reg peak) ----
        const int tn = t + ngrp;
        const bool pf = tn < ntiles;
        uint32_t pv2[32];
        float2 px[3];
        if (pf) {
            const float4* hsrc = (const float4*)(hidden + (size_t)tn * 32 * 256);
            {
                float4 tmp[8];
#pragma unroll
                for (int j = 0; j < 8; j++) tmp[j] = hsrc[j * 128 + pt];
#pragma unroll
                for (int j = 0; j < 8; j++) {
                    pv2[2 * j]     = pack2(tmp[j].x, tmp[j].y);
                    pv2[2 * j + 1] = pack2(tmp[j].z, tmp[j].w);
                }
            }
            {
                float4 tmp[8];
#pragma unroll
                for (int j = 0; j < 8; j++) tmp[j] = hsrc[(j + 8) * 128 + pt];
#pragma unroll
                for (int j = 0; j < 8; j++) {
                    pv2[16 + 2 * j] = pack2(tmp[j].x, tmp[j].y);
                    pv2[17 + 2 * j] = pack2(tmp[j].z, tmp[j].w);
                }
            }
            const float2* xsrc = (const float2*)(xin + (size_t)tn * 32 * 24);
#pragma unroll
            for (int j = 0; j < 3; j++) px[j] = xsrc[j * 128 + pt];
        }

        BAR_GRP(barid);   // whole group done reading A before scratch (aliased) write

        // ---- write 32x16 partials to this warp's scratch region ----
#pragma unroll
        for (int nt = 0; nt < 2; nt++)
#pragma unroll
            for (int half = 0; half < 2; half++) {
                const int i = nt * 8 + half * 4;
                const uint32_t base = scrW + (uint32_t)((g + half * 16) * 72 + (nt * 8 + c0) * 4);
                stsf2(base,          pa[i + 0], pa[i + 1]);
                stsf2(base + 8 * 72, pa[i + 2], pa[i + 3]);
            }
        BAR_GRP(barid);   // partials visible

        // ---- sum 4 partials; warp nq handles tile rows nq*8+g; quad = 1 row ----
        float l[4];
        l[0] = sbproj[c0]; l[1] = sbproj[c0 + 1];
        l[2] = sbproj[8 + c0]; l[3] = sbproj[9 + c0];
        {
            const uint32_t rbase = ab + (uint32_t)((nq * 8 + g) * 72);
#pragma unroll
            for (int j = 0; j < 4; j++) {
                float p0, p1;
                ldsf2(p0, p1, rbase + j * 2304 + c0 * 4);
                l[0] += p0; l[1] += p1;
                ldsf2(p0, p1, rbase + j * 2304 + (8 + c0) * 4);
                l[2] += p0; l[3] += p1;
            }
        }

        {
            const bool v1 = (8 + c0) < 12;
            if (!v1) { l[2] = l[3] = -1e30f; }

            float mx = fmaxf(fmaxf(l[0], l[1]), fmaxf(l[2], l[3]));
            mx = fmaxf(mx, __shfl_xor_sync(0xFFFFFFFFu, mx, 1));
            mx = fmaxf(mx, __shfl_xor_sync(0xFFFFFFFFu, mx, 2));

            float s = 0.f;
#pragma unroll
            for (int j = 0; j < 4; j++) { l[j] = __expf(l[j] - mx); s += l[j]; }
            s += __shfl_xor_sync(0xFFFFFFFFu, s, 1);
            s += __shfl_xor_sync(0xFFFFFFFFu, s, 2);
            const float inv = __fdividef(1.0f, s);

            float* o = out + (r0 + nq * 8 + g) * 12;
            *(float2*)(o + c0) = make_float2(l[0] * inv, l[1] * inv);
            if (v1) *(float2*)(o + 8 + c0) = make_float2(l[2] * inv, l[3] * inv);
        }

        BAR_GRP(barid);   // scratch reads done before next tile's A staging

        // ---- store prefetched next-tile A/x into SMEM ----
        if (pf) {
#pragma unroll
            for (int j = 0; j < 16; j++) {
                const int f4 = j * 128 + pt;
                sts64(ab + (uint32_t)(f4 >> 6) * A_STRIDE + (f4 & 63) * 8,
                      pv2[2 * j], pv2[2 * j + 1]);
            }
#pragma unroll
            for (int j = 0; j < 3; j++) {
                const int j2 = j * 128 + pt;
                const int row = j2 / 12, cc = j2 % 12;
                sts32(ab + (uint32_t)row * A_STRIDE + 512 + cc * 4, pack2(px[j].x, px[j].y));
            }
        }
    }
}

extern "C" void kernel_launch(void* const* d_in, const int* in_sizes, int n_in,
                              void* d_out, int out_size) {
    const float* x      = (const float*)d_in[0];
    const float* hidden = (const float*)d_in[1];
    const float* W_ih   = (const float*)d_in[2];
    const float* b_ih   = (const float*)d_in[3];
    const float* W_hh   = (const float*)d_in[4];
    const float* b_hh   = (const float*)d_in[5];
    const float* W_proj = (const float*)d_in[6];
    const float* b_proj = (const float*)d_in[7];

    const int N = in_sizes[0] / 24;            // 524288
    float* out   = (float*)d_out;              // [N,12] softmax
    float* h_out = out + (size_t)N * 12;       // [N,256] h_new

    cudaFuncSetAttribute(rnn_kernel, cudaFuncAttributeMaxDynamicSharedMemorySize, SM_TOTAL);

    prep_kernel<<<293, 256>>>(W_ih, W_hh, W_proj);               // 74848 elems (guarded)
    rnn_kernel<<<152, 512, SM_TOTAL>>>(x, hidden, b_ih, b_hh, b_proj,
                                       out, h_out, N / 32);      // persistent; tiles of 32 rows
}

// round 15
// speedup vs baseline: 1.1119x; 1.0324x over previous
#include <cuda_runtime.h>
#include <cuda_fp16.h>
#include <cstdint>

// ---------------- SMEM layout (bytes) ----------------
#define SM_BIAS   0                    // 256 floats
#define SM_BPROJ  1024                 // 16 floats
#define SM_W      1152                 // W image: 256 rows x 592B = 151552
#define W_STRIDE  592                  // 296 halves (288 used + pad), conflict-free ldmatrix
#define SM_WP     (1152 + 151552)      // 152704: W_proj 16 rows x 528B = 8448
#define WP_STRIDE 528
#define SM_A      (152704 + 8448)      // 161152: A fp16 staging, 3 groups x 18944
#define A_GRP     18944                // 32 rows x 592B (h cols 0..255, x 256..279, zero 280..295)
#define A_STRIDE  592
#define SM_TOTAL  (161152 + 3 * 18944) // 217984

#define W_U4   9472                    // 151552 / 16
#define WP_U4  528                     // 8448 / 16

// Pre-converted fp16 weight images (static device scratch — no allocation)
__device__ uint4 g_w[W_U4];            // [n 0..255][k 0..295 halves]; k<256=W_hh, 256..279=W_ih, pad 0
__device__ uint4 g_wp[WP_U4];          // [n 0..15][k 0..263 halves]; n<12,k<256=W_proj else 0

static __device__ __forceinline__ uint32_t smem_u32(const void* p) {
    uint32_t r;
    asm("{ .reg .u64 t; cvta.to.shared.u64 t, %1; cvt.u32.u64 %0, t; }" : "=r"(r) : "l"(p));
    return r;
}
static __device__ __forceinline__ uint32_t pack2(float a, float b) {
    __half2 h = __floats2half2_rn(a, b);
    return *reinterpret_cast<uint32_t*>(&h);
}
static __device__ __forceinline__ float2 unpack2(uint32_t v) {
    __half2 h = *reinterpret_cast<__half2*>(&v);
    return __half22float2(h);
}
static __device__ __forceinline__ void cp16(uint32_t dst, const void* src) {
    asm volatile("cp.async.cg.shared.global [%0], [%1], 16;" :: "r"(dst), "l"(src));
}
#define CP_COMMIT()  asm volatile("cp.async.commit_group;" ::: "memory")
#define CP_WAIT(n)   asm volatile("cp.async.wait_group %0;" :: "n"(n) : "memory")

static __device__ __forceinline__ void lds32(uint32_t& v, uint32_t a) {
    asm volatile("ld.shared.b32 %0, [%1];" : "=r"(v) : "r"(a));
}
static __device__ __forceinline__ void ldsf2(float& v0, float& v1, uint32_t a) {
    asm volatile("ld.shared.v2.f32 {%0,%1}, [%2];" : "=f"(v0), "=f"(v1) : "r"(a));
}
static __device__ __forceinline__ void stsf2(uint32_t a, float v0, float v1) {
    asm volatile("st.shared.v2.f32 [%0], {%1,%2};" :: "r"(a), "f"(v0), "f"(v1));
}
static __device__ __forceinline__ void sts32(uint32_t a, uint32_t v) {
    asm volatile("st.shared.b32 [%0], %1;" :: "r"(a), "r"(v));
}
static __device__ __forceinline__ void sts64(uint32_t a, uint32_t v0, uint32_t v1) {
    asm volatile("st.shared.v2.b32 [%0], {%1,%2};" :: "r"(a), "r"(v0), "r"(v1));
}
static __device__ __forceinline__ void ldmatrix4(uint32_t& a0, uint32_t& a1,
                                                 uint32_t& a2, uint32_t& a3, uint32_t addr) {
    asm volatile("ldmatrix.sync.aligned.m8n8.x4.shared.b16 {%0,%1,%2,%3}, [%4];"
                 : "=r"(a0), "=r"(a1), "=r"(a2), "=r"(a3) : "r"(addr));
}
#define MMA16816(c0, c1, c2, c3, a0, a1, a2, a3, b0, b1)                          \
    asm volatile("mma.sync.aligned.m16n8k16.row.col.f32.f16.f16.f32 "             \
                 "{%0,%1,%2,%3},{%4,%5,%6,%7},{%8,%9},{%0,%1,%2,%3};"             \
                 : "+f"(c0), "+f"(c1), "+f"(c2), "+f"(c3)                          \
                 : "r"(a0), "r"(a1), "r"(a2), "r"(a3), "r"(b0), "r"(b1))
#define BAR_GRP(id) asm volatile("bar.sync %0, 128;" :: "r"(id) : "memory")

static __device__ __forceinline__ uint32_t tanh16x2(uint32_t z) {
    uint32_t r;
    asm("tanh.approx.f16x2 %0, %1;" : "=r"(r) : "r"(z));
    return r;
}

// ================= prep: fp32 -> fp16 padded weight images =================
__global__ void prep_kernel(const float* __restrict__ W_ih, const float* __restrict__ W_hh,
                            const float* __restrict__ W_proj) {
    int idx = blockIdx.x * 256 + threadIdx.x;
    if (idx < 256 * 296) {
        int n = idx / 296, k = idx % 296;
        float v = 0.0f;
        if (k < 256)      v = W_hh[n * 256 + k];
        else if (k < 280) v = W_ih[n * 24 + (k - 256)];
        reinterpret_cast<__half*>(g_w)[idx] = __float2half_rn(v);
    } else if (idx < 256 * 296 + 16 * 264) {
        int r = idx - 256 * 296;          // 0 .. 4223
        int n = r / 264, k = r % 264;
        float v = (n < 12 && k < 256) ? W_proj[n * 256 + k] : 0.0f;
        reinterpret_cast<__half*>(g_wp)[r] = __float2half_rn(v);
    }
}

// ====== persistent fused kernel: 384 thr; 3 groups x 4 warps; f16x2 tanh epilogue ======
__global__ void __launch_bounds__(384, 1)
rnn_kernel(const float* __restrict__ xin, const float* __restrict__ hidden,
           const float* __restrict__ b_ih, const float* __restrict__ b_hh,
           const float* __restrict__ b_proj,
           float* __restrict__ out, float* __restrict__ h_out, int ntiles) {
    extern __shared__ char smem[];
    const uint32_t sb = smem_u32(smem);
    float* sbias  = reinterpret_cast<float*>(smem + SM_BIAS);
    float* sbproj = reinterpret_cast<float*>(smem + SM_BPROJ);

    const int tid  = threadIdx.x;
    const int w    = tid >> 5;
    const int lane = tid & 31;
    const int g    = lane >> 2;          // fragment row group 0..7
    const int c0   = (lane & 3) * 2;     // fragment col base 0,2,4,6
    const int grp  = w >> 2;             // 0..2
    const int nq   = w & 3;              // N-quarter: cols [nq*64, nq*64+64)
    const int pt   = (nq << 5) | lane;   // 0..127 within group

    // ---- resident W load (once per CTA) ----
#pragma unroll
    for (int it = 0; it < 25; it++) {
        int i = tid + it * 384;
        if (i < W_U4) cp16(sb + SM_W + i * 16, g_w + i);
    }
#pragma unroll
    for (int it = 0; it < 2; it++) {
        int i = tid + it * 384;
        if (i < WP_U4) cp16(sb + SM_WP + i * 16, g_wp + i);
    }
    CP_COMMIT();
    if (tid < 256) sbias[tid] = b_ih[tid] + b_hh[tid];
    if (tid < 16) sbproj[tid] = (tid < 12) ? b_proj[tid] : 0.0f;
    CP_WAIT(0);
    __syncthreads();

    // ---- ldmatrix B base (matrix m = lane>>3: nt-parity m>>1, k-half m&1) ----
    const int mrole = lane >> 3, mrow = lane & 7;
    const uint32_t wq0 = sb + SM_W +
        (uint32_t)((nq * 64 + (mrole >> 1) * 8 + mrow) * W_STRIDE) + (mrole & 1) * 16;
    // proj B bases: this quarter's K-chunk, n-tiles 0 and 1
    const uint32_t pbase = sb + SM_WP + (uint32_t)(nq * 128) + (lane & 3) * 4;
    const uint32_t pb0 = pbase + (uint32_t)(g * WP_STRIDE);
    const uint32_t pb1 = pbase + (uint32_t)((8 + g) * WP_STRIDE);
    // this group's A staging buffer; proj-exchange scratch aliases it (dead after k-loop)
    const uint32_t ab   = sb + SM_A + (uint32_t)grp * A_GRP;
    const uint32_t am0  = ab + (uint32_t)(lane & 15) * A_STRIDE + (lane >> 4) * 16;
    const uint32_t am1  = am0 + 16 * A_STRIDE;
    const uint32_t scrW = ab + (uint32_t)nq * 2304;
    // per-thread pad-zero slot (bytes 560..575 of each row; scratch clobbers rows 0..14)
    const uint32_t padz = ab + (uint32_t)(pt >> 2) * A_STRIDE + 560 + (pt & 3) * 4;
    const int barid = grp + 1;

    const int ngrp = gridDim.x * 3;
    int t = blockIdx.x * 3 + grp;

    // ---- prologue: stage first tile ----
    {
        const float4* hsrc = (const float4*)(hidden + (size_t)t * 32 * 256);
#pragma unroll
        for (int j = 0; j < 16; j++) {
            const int f4 = j * 128 + pt;
            float4 v = hsrc[f4];
            sts64(ab + (uint32_t)(f4 >> 6) * A_STRIDE + (f4 & 63) * 8,
                  pack2(v.x, v.y), pack2(v.z, v.w));
        }
        const float2* xsrc = (const float2*)(xin + (size_t)t * 32 * 24);
#pragma unroll
        for (int j = 0; j < 3; j++) {
            const int j2 = j * 128 + pt;
            const int row = j2 / 12, cc = j2 % 12;
            float2 f = xsrc[j2];
            sts32(ab + (uint32_t)row * A_STRIDE + 512 + cc * 4, pack2(f.x, f.y));
        }
        sts32(padz, 0u);
    }

    for (; t < ntiles; t += ngrp) {
        const size_t r0 = (size_t)t * 32;

        // ---- acc init = bias ----
        float acc[64];
#pragma unroll
        for (int q = 0; q < 4; q++)
#pragma unroll
            for (int nt = 0; nt < 2; nt++) {
                float2 bb = *(const float2*)(sbias + nq * 64 + q * 16 + nt * 8 + c0);
                const int i = q * 16 + nt * 8;
                acc[i + 0] = bb.x; acc[i + 1] = bb.y; acc[i + 2] = bb.x; acc[i + 3] = bb.y;
                acc[i + 4] = bb.x; acc[i + 5] = bb.y; acc[i + 6] = bb.x; acc[i + 7] = bb.y;
            }

        BAR_GRP(barid);   // B0: staged A (and pad zeros) visible to whole group

        // ---- MMA1: uniform 18 k-steps, A via ldmatrix (h cols 0..255, x 256..279, pad zeros) ----
#pragma unroll
        for (int ks = 0; ks < 18; ks++) {
            uint32_t a0, a1, a2, a3, a4, a5, a6, a7;
            ldmatrix4(a0, a1, a2, a3, am0 + ks * 32);
            ldmatrix4(a4, a5, a6, a7, am1 + ks * 32);
#pragma unroll
            for (int q = 0; q < 4; q++) {
                uint32_t b0, b1, b2, b3;
                ldmatrix4(b0, b1, b2, b3,
                          wq0 + (uint32_t)q * (16 * W_STRIDE) + ks * 32);
                const int i = q * 16;
                MMA16816(acc[i + 0], acc[i + 1], acc[i + 2], acc[i + 3],
                         a0, a1, a2, a3, b0, b1);
                MMA16816(acc[i + 4], acc[i + 5], acc[i + 6], acc[i + 7],
                         a4, a5, a6, a7, b0, b1);
                MMA16816(acc[i + 8], acc[i + 9], acc[i + 10], acc[i + 11],
                         a0, a1, a2, a3, b2, b3);
                MMA16816(acc[i + 12], acc[i + 13], acc[i + 14], acc[i + 15],
                         a4, a5, a6, a7, b2, b3);
            }
        }

        // ---- tanh in f16x2 (halves MUFU); hh feeds proj directly ----
        uint32_t hh[32];
#pragma unroll
        for (int j = 0; j < 32; j++)
            hh[j] = tanh16x2(pack2(acc[2 * j], acc[2 * j + 1]));

        // ---- store h_new fp32 (unpack from f16x2) ----
        float* hp = h_out + (r0 + g) * 256 + nq * 64;
#pragma unroll
        for (int q = 0; q < 4; q++)
#pragma unroll
            for (int nt = 0; nt < 2; nt++) {
                const int j = q * 8 + nt * 4;
                const int n = q * 16 + nt * 8 + c0;
                *(float2*)(hp + n)            = unpack2(hh[j + 0]);
                *(float2*)(hp + 8 * 256 + n)  = unpack2(hh[j + 1]);
                *(float2*)(hp + 16 * 256 + n) = unpack2(hh[j + 2]);
                *(float2*)(hp + 24 * 256 + n) = unpack2(hh[j + 3]);
            }

        // ---- proj partials: A frags straight from hh ----
        float pa[16];
#pragma unroll
        for (int i = 0; i < 16; i++) pa[i] = 0.0f;
#pragma unroll
        for (int pk = 0; pk < 4; pk++) {
            const int j = pk * 8;
            uint32_t b00, b01, b10, b11;
            lds32(b00, pb0 + pk * 32); lds32(b01, pb0 + pk * 32 + 16);
            lds32(b10, pb1 + pk * 32); lds32(b11, pb1 + pk * 32 + 16);
            MMA16816(pa[0],  pa[1],  pa[2],  pa[3],
                     hh[j + 0], hh[j + 1], hh[j + 4], hh[j + 5], b00, b01);
            MMA16816(pa[4],  pa[5],  pa[6],  pa[7],
                     hh[j + 2], hh[j + 3], hh[j + 6], hh[j + 7], b00, b01);
            MMA16816(pa[8],  pa[9],  pa[10], pa[11],
                     hh[j + 0], hh[j + 1], hh[j + 4], hh[j + 5], b10, b11);
            MMA16816(pa[12], pa[13], pa[14], pa[15],
                     hh[j + 2], hh[j + 3], hh[j + 6], hh[j + 7], b10, b11);
        }

        // ---- prefetch next tile's A/x into registers (acc/hh now dead) ----
        const int tn = t + ngrp;
        const bool pf = tn < ntiles;
        uint32_t pv2[32];
        float2 px[3];
        if (pf) {
            const float4* hsrc = (const float4*)(hidden + (size_t)tn * 32 * 256);
            {
                float4 tmp[8];
#pragma unroll
                for (int j = 0; j < 8; j++) tmp[j] = hsrc[j * 128 + pt];
#pragma unroll
                for (int j = 0; j < 8; j++) {
                    pv2[2 * j]     = pack2(tmp[j].x, tmp[j].y);
                    pv2[2 * j + 1] = pack2(tmp[j].z, tmp[j].w);
                }
            }
            {
                float4 tmp[8];
#pragma unroll
                for (int j = 0; j < 8; j++) tmp[j] = hsrc[(j + 8) * 128 + pt];
#pragma unroll
                for (int j = 0; j < 8; j++) {
                    pv2[16 + 2 * j] = pack2(tmp[j].x, tmp[j].y);
                    pv2[17 + 2 * j] = pack2(tmp[j].z, tmp[j].w);
                }
            }
            const float2* xsrc = (const float2*)(xin + (size_t)tn * 32 * 24);
#pragma unroll
            for (int j = 0; j < 3; j++) px[j] = xsrc[j * 128 + pt];
        }

        BAR_GRP(barid);   // B1: whole group done reading A before scratch (aliased) write

        // ---- write 32x16 partials to this warp's scratch region ----
#pragma unroll
        for (int nt = 0; nt < 2; nt++)
#pragma unroll
            for (int half = 0; half < 2; half++) {
                const int i = nt * 8 + half * 4;
                const uint32_t base = scrW + (uint32_t)((g + half * 16) * 72 + (nt * 8 + c0) * 4);
                stsf2(base,          pa[i + 0], pa[i + 1]);
                stsf2(base + 8 * 72, pa[i + 2], pa[i + 3]);
            }
        BAR_GRP(barid);   // B2: partials visible

        // ---- sum 4 partials; warp nq handles tile rows nq*8+g; quad = 1 row ----
        float l[4];
        l[0] = sbproj[c0]; l[1] = sbproj[c0 + 1];
        l[2] = sbproj[8 + c0]; l[3] = sbproj[9 + c0];
        {
            const uint32_t rbase = ab + (uint32_t)((nq * 8 + g) * 72);
#pragma unroll
            for (int j = 0; j < 4; j++) {
                float p0, p1;
                ldsf2(p0, p1, rbase + j * 2304 + c0 * 4);
                l[0] += p0; l[1] += p1;
                ldsf2(p0, p1, rbase + j * 2304 + (8 + c0) * 4);
                l[2] += p0; l[3] += p1;
            }
        }

        {
            const bool v1 = (8 + c0) < 12;
            if (!v1) { l[2] = l[3] = -1e30f; }

            float mx = fmaxf(fmaxf(l[0], l[1]), fmaxf(l[2], l[3]));
            mx = fmaxf(mx, __shfl_xor_sync(0xFFFFFFFFu, mx, 1));
            mx = fmaxf(mx, __shfl_xor_sync(0xFFFFFFFFu, mx, 2));

            float s = 0.f;
#pragma unroll
            for (int j = 0; j < 4; j++) { l[j] = __expf(l[j] - mx); s += l[j]; }
            s += __shfl_xor_sync(0xFFFFFFFFu, s, 1);
            s += __shfl_xor_sync(0xFFFFFFFFu, s, 2);
            const float inv = __fdividef(1.0f, s);

            float* o = out + (r0 + nq * 8 + g) * 12;
            *(float2*)(o + c0) = make_float2(l[0] * inv, l[1] * inv);
            if (v1) *(float2*)(o + 8 + c0) = make_float2(l[2] * inv, l[3] * inv);
        }

        BAR_GRP(barid);   // B3: scratch reads done before next tile's A staging

        // ---- store prefetched next-tile A/x + RE-ZERO PAD (scratch clobbered rows 0..14 pads) ----
        if (pf) {
#pragma unroll
            for (int j = 0; j < 16; j++) {
                const int f4 = j * 128 + pt;
                sts64(ab + (uint32_t)(f4 >> 6) * A_STRIDE + (f4 & 63) * 8,
                      pv2[2 * j], pv2[2 * j + 1]);
            }
#pragma unroll
            for (int j = 0; j < 3; j++) {
                const int j2 = j * 128 + pt;
                const int row = j2 / 12, cc = j2 % 12;
                sts32(ab + (uint32_t)row * A_STRIDE + 512 + cc * 4, pack2(px[j].x, px[j].y));
            }
            sts32(padz, 0u);   // FIX: pad bytes 560..575 were clobbered by aliased scratch
        }
    }
}

extern "C" void kernel_launch(void* const* d_in, const int* in_sizes, int n_in,
                              void* d_out, int out_size) {
    const float* x      = (const float*)d_in[0];
    const float* hidden = (const float*)d_in[1];
    const float* W_ih   = (const float*)d_in[2];
    const float* b_ih   = (const float*)d_in[3];
    const float* W_hh   = (const float*)d_in[4];
    const float* b_hh   = (const float*)d_in[5];
    const float* W_proj = (const float*)d_in[6];
    const float* b_proj = (const float*)d_in[7];

    const int N = in_sizes[0] / 24;            // 524288
    float* out   = (float*)d_out;              // [N,12] softmax
    float* h_out = out + (size_t)N * 12;       // [N,256] h_new

    cudaFuncSetAttribute(rnn_kernel, cudaFuncAttributeMaxDynamicSharedMemorySize, SM_TOTAL);

    prep_kernel<<<313, 256>>>(W_ih, W_hh, W_proj);               // guarded
    rnn_kernel<<<152, 384, SM_TOTAL>>>(x, hidden, b_ih, b_hh, b_proj,
                                       out, h_out, N / 32);      // persistent; tiles of 32 rows
}